// round 2
// baseline (speedup 1.0000x reference)
#include <cuda_runtime.h>
#include <math.h>

// acc[bq][n], bq = b*2 + q. Capacity 2M floats (need 32*30000 = 960K).
#define ACC_CAP (1 << 21)
#define W_CAP   (1 << 16)
__device__ __align__(16) float g_acc[ACC_CAP];
__device__ float g_W[W_CAP];

#define MAX_D 256

// K0: blocks [0, nBQ) compute W[bq][*] (warp-per-t, lanes over d);
//     blocks [nBQ, ...) zero the accumulator with float4 stores.
__global__ void k_init(const int* __restrict__ r_index,
                       const float* __restrict__ rel_emb,
                       const float* __restrict__ rel_proj,
                       const float* __restrict__ w_out,
                       int nBQ, int R, int D, int accN)
{
    if ((int)blockIdx.x < nBQ) {
        int bq = blockIdx.x;
        __shared__ float v[MAX_D];
        int r = r_index[bq];
        for (int d = threadIdx.x; d < D; d += blockDim.x)
            v[d] = rel_emb[(size_t)r * D + d] * w_out[d];
        __syncthreads();
        int warp = threadIdx.x >> 5;
        int lane = threadIdx.x & 31;
        int nwarps = blockDim.x >> 5;
        for (int t = warp; t < R; t += nwarps) {
            const float* p = rel_proj + (size_t)t * D;
            float s = 0.0f;
            for (int d = lane; d < D; d += 32)
                s += v[d] * p[d];
            #pragma unroll
            for (int o = 16; o > 0; o >>= 1)
                s += __shfl_xor_sync(0xFFFFFFFFu, s, o);
            if (lane == 0) g_W[bq * R + t] = s;
        }
    } else {
        int i = ((int)blockIdx.x - nBQ) * blockDim.x + threadIdx.x;
        int n4 = accN >> 2;
        float4* acc4 = (float4*)g_acc;
        if (i < n4) acc4[i] = make_float4(0.f, 0.f, 0.f, 0.f);
        // tail (accN not multiple of 4)
        int tail = accN & 3;
        if (i < tail) g_acc[(n4 << 2) + i] = 0.0f;
    }
}

// K1: per-edge scatter. dst and edge_type loaded ONLY on a src match (~E/N
// expected matches per (bq)), so the hot path reads just the src row (E ints).
__global__ void k_scatter(const int* __restrict__ e_index,
                          const int* __restrict__ edge_index,
                          const int* __restrict__ edge_type,
                          int E, int nBQ, int R, int N)
{
    __shared__ int s_e[64];
    int tid = threadIdx.x;
    if (tid < nBQ) s_e[tid] = e_index[tid];
    __syncthreads();

    int e = blockIdx.x * blockDim.x + tid;
    if (e >= E) return;

    int src = edge_index[e];            // row 0 of (2, E)
    int t = -1, dst = -1;
    #pragma unroll 4
    for (int bq = 0; bq < nBQ; bq++) {
        if (src == s_e[bq]) {
            if (t < 0) {
                t   = edge_type[e];
                dst = edge_index[E + e];   // row 1, lazy
            }
            atomicAdd(&g_acc[(size_t)bq * N + dst], g_W[bq * R + t]);
        }
    }
}

__device__ __forceinline__ float final_elem(float a1, float a2)
{
    float t1 = 1.0f / (1.0f + __expf(-a1));
    float t2 = 1.0f / (1.0f + __expf(-a2));
    float tp = t1 * t2;
    const float EPS = 1e-10f;
    return __logf((tp + EPS) / (1.0f - tp + EPS));
}

// K2 (vectorized): requires N % 4 == 0. Each thread: one float4 from each of
// the two acc rows, one float4 out.
__global__ void k_final4(float* __restrict__ out, int B, int N)
{
    int i = blockIdx.x * blockDim.x + threadIdx.x;
    int N4 = N >> 2;
    int total = B * N4;
    if (i >= total) return;
    int b  = i / N4;
    int n4 = i - b * N4;
    const float4* acc4 = (const float4*)g_acc;
    float4 a1 = acc4[(size_t)(2 * b)     * N4 + n4];
    float4 a2 = acc4[(size_t)(2 * b + 1) * N4 + n4];
    float4 o;
    o.x = final_elem(a1.x, a2.x);
    o.y = final_elem(a1.y, a2.y);
    o.z = final_elem(a1.z, a2.z);
    o.w = final_elem(a1.w, a2.w);
    ((float4*)out)[i] = o;
}

// scalar fallback if N % 4 != 0
__global__ void k_final1(float* __restrict__ out, int B, int N)
{
    int i = blockIdx.x * blockDim.x + threadIdx.x;
    int total = B * N;
    if (i >= total) return;
    int b = i / N;
    int n = i - b * N;
    float a1 = g_acc[(size_t)(2 * b)     * N + n];
    float a2 = g_acc[(size_t)(2 * b + 1) * N + n];
    out[i] = final_elem(a1, a2);
}

extern "C" void kernel_launch(void* const* d_in, const int* in_sizes, int n_in,
                              void* d_out, int out_size)
{
    // Input order: e_index, r_index, edge_index, edge_type, [num_nodes], rel_emb, rel_proj, w_out
    const int* e_index    = (const int*)d_in[0];
    const int* r_index    = (const int*)d_in[1];
    const int* edge_index = (const int*)d_in[2];
    const int* edge_type  = (const int*)d_in[3];
    int off = (n_in >= 8) ? 5 : 4;
    const float* rel_emb  = (const float*)d_in[off];
    const float* rel_proj = (const float*)d_in[off + 1];
    const float* w_out    = (const float*)d_in[off + 2];

    int nBQ = in_sizes[0];               // B*2
    int B   = nBQ / 2;
    int E   = in_sizes[3];               // edge_type is [E]
    int D   = in_sizes[off + 2];         // w_out is [D]
    int R   = in_sizes[off] / D;         // rel_emb is [R, D]
    int N   = out_size / B;              // output is [B, N]

    int accN = nBQ * N;

    const int TPB = 256;
    int zeroBlocks = ((accN >> 2) + TPB - 1) / TPB;
    int gridInit   = nBQ + zeroBlocks;
    int gridScat   = (E + TPB - 1) / TPB;

    k_init   <<<gridInit, TPB>>>(r_index, rel_emb, rel_proj, w_out, nBQ, R, D, accN);
    k_scatter<<<gridScat, TPB>>>(e_index, edge_index, edge_type, E, nBQ, R, N);
    if ((N & 3) == 0) {
        int gridFinal = (B * (N >> 2) + TPB - 1) / TPB;
        k_final4<<<gridFinal, TPB>>>((float*)d_out, B, N);
    } else {
        int gridFinal = (B * N + TPB - 1) / TPB;
        k_final1<<<gridFinal, TPB>>>((float*)d_out, B, N);
    }
}

// round 3
// speedup vs baseline: 1.8275x; 1.8275x over previous
#include <cuda_runtime.h>
#include <math.h>

// acc[bq][n]; starts zero (static init), and k_fix restores touched entries to
// zero each call, so the zero-invariant holds across graph replays.
#define ACC_CAP  (1 << 21)
#define LIST_CAP (1 << 20)
__device__ float g_acc[ACC_CAP];
__device__ int2  g_list[LIST_CAP];
__device__ int   g_cnt;   // zero-initialized; reset by k_fix each call

__device__ __forceinline__ float final_elem(float a1, float a2)
{
    float t1 = 1.0f / (1.0f + __expf(-a1));
    float t2 = 1.0f / (1.0f + __expf(-a2));
    float tp = t1 * t2;
    const float EPS = 1e-10f;
    return __logf((tp + EPS) / (1.0f - tp + EPS));
}

// K1: blocks [0, scatBlocks) scan edges; on the rare src match the warp
// cooperatively computes dot(rel_emb[r]*w_out, rel_proj[t]) and atomically
// accumulates into acc, recording the touched (bq, dst) pair.
// Blocks [scatBlocks, ...) fill the output with final_elem(0,0) (the value at
// every untouched node).
__global__ void k_main(const int* __restrict__ e_index,
                       const int* __restrict__ r_index,
                       const int* __restrict__ edge_index,
                       const int* __restrict__ edge_type,
                       const float* __restrict__ rel_emb,
                       const float* __restrict__ rel_proj,
                       const float* __restrict__ w_out,
                       float* __restrict__ out,
                       int E, int nBQ, int D, int N, int outN, int scatBlocks)
{
    int tid = threadIdx.x;
    int bid = blockIdx.x;

    if (bid < scatBlocks) {
        __shared__ int s_e[64];
        __shared__ int s_r[64];
        if (tid < nBQ) { s_e[tid] = e_index[tid]; s_r[tid] = r_index[tid]; }
        __syncthreads();

        int e   = bid * blockDim.x + tid;
        int src = (e < E) ? edge_index[e] : -1;

        unsigned long long mm = 0ull;
        for (int bq = 0; bq < nBQ; bq++)
            mm |= ((unsigned long long)(src == s_e[bq])) << bq;

        int lane = tid & 31;
        unsigned any = __ballot_sync(0xFFFFFFFFu, mm != 0ull);
        while (any) {
            int leader = __ffs(any) - 1;
            any &= any - 1;
            unsigned long long lm = __shfl_sync(0xFFFFFFFFu, mm, leader);
            int le  = __shfl_sync(0xFFFFFFFFu, e, leader);
            int t   = edge_type[le];
            int dst = edge_index[E + le];
            const float* pt = rel_proj + (size_t)t * D;
            while (lm) {
                int bq = __ffsll(lm) - 1;
                lm &= lm - 1;
                int r = s_r[bq];
                const float* pr = rel_emb + (size_t)r * D;
                float s = 0.0f;
                for (int d = lane; d < D; d += 32)
                    s += pr[d] * w_out[d] * pt[d];
                #pragma unroll
                for (int o = 16; o > 0; o >>= 1)
                    s += __shfl_xor_sync(0xFFFFFFFFu, s, o);
                if (lane == 0) {
                    atomicAdd(&g_acc[(size_t)bq * N + dst], s);
                    int idx = atomicAdd(&g_cnt, 1);
                    if (idx < LIST_CAP) g_list[idx] = make_int2(bq, dst);
                }
            }
        }
    } else {
        // const fill of out
        float cv = final_elem(0.0f, 0.0f);
        int i  = (bid - scatBlocks) * blockDim.x + tid;
        int n4 = outN >> 2;
        if (i < n4) ((float4*)out)[i] = make_float4(cv, cv, cv, cv);
        int tail = outN & 3;
        if (i < tail) out[(n4 << 2) + i] = cv;
    }
}

// K2: single block. Phase 1: recompute output at touched nodes. Phase 2
// (after sync): zero the touched acc entries and reset the list counter,
// restoring the zero-invariant for the next replay.
__global__ void k_fix(float* __restrict__ out, int N)
{
    int cnt = g_cnt;
    if (cnt > LIST_CAP) cnt = LIST_CAP;

    for (int i = threadIdx.x; i < cnt; i += blockDim.x) {
        int2 en = g_list[i];
        int b = en.x >> 1, n = en.y;
        float a1 = g_acc[(size_t)(2 * b)     * N + n];
        float a2 = g_acc[(size_t)(2 * b + 1) * N + n];
        out[(size_t)b * N + n] = final_elem(a1, a2);
    }
    __syncthreads();
    for (int i = threadIdx.x; i < cnt; i += blockDim.x) {
        int2 en = g_list[i];
        int b = en.x >> 1, n = en.y;
        g_acc[(size_t)(2 * b)     * N + n] = 0.0f;
        g_acc[(size_t)(2 * b + 1) * N + n] = 0.0f;
    }
    __syncthreads();
    if (threadIdx.x == 0) g_cnt = 0;
}

extern "C" void kernel_launch(void* const* d_in, const int* in_sizes, int n_in,
                              void* d_out, int out_size)
{
    // Input order: e_index, r_index, edge_index, edge_type, [num_nodes], rel_emb, rel_proj, w_out
    const int* e_index    = (const int*)d_in[0];
    const int* r_index    = (const int*)d_in[1];
    const int* edge_index = (const int*)d_in[2];
    const int* edge_type  = (const int*)d_in[3];
    int off = (n_in >= 8) ? 5 : 4;
    const float* rel_emb  = (const float*)d_in[off];
    const float* rel_proj = (const float*)d_in[off + 1];
    const float* w_out    = (const float*)d_in[off + 2];

    int nBQ = in_sizes[0];               // B*2
    int B   = nBQ / 2;
    int E   = in_sizes[3];               // edge_type is [E]
    int D   = in_sizes[off + 2];         // w_out is [D]
    int N   = out_size / B;              // output is [B, N]
    int outN = out_size;

    const int TPB = 256;
    int scatBlocks = (E + TPB - 1) / TPB;
    int fillBlocks = ((outN >> 2) + TPB - 1) / TPB + 1;
    int grid = scatBlocks + fillBlocks;

    k_main<<<grid, TPB>>>(e_index, r_index, edge_index, edge_type,
                          rel_emb, rel_proj, w_out, (float*)d_out,
                          E, nBQ, D, N, outN, scatBlocks);
    k_fix<<<1, 256>>>((float*)d_out, N);
}